// round 1
// baseline (speedup 1.0000x reference)
#include <cuda_runtime.h>
#include <math.h>

#define BATCH 8192

// ---------------- scratch (device globals: allowed) ----------------
__device__ float  d_conv1raw[BATCH * 6 * 784];   // [B,6,28,28]
__device__ float  d_pool1   [BATCH * 6 * 196];   // [B,6,14,14]
__device__ float  d_conv2raw[BATCH * 16 * 100];  // [B,16,10,10]
__device__ float  d_pool2   [BATCH * 16 * 25];   // [B,16,5,5]
__device__ float  d_conv3raw[BATCH * 120];       // [B,120]
__device__ float  d_w3s     [120 * 400];         // binarized conv3 weights
__device__ double d_sum  [142];                  // 6 + 16 + 120 channel sums
__device__ double d_sumsq[142];
__device__ float  d_bnA[142];                    // per-channel scale
__device__ float  d_bnC[142];                    // per-channel shift

__device__ __forceinline__ float fsign(float v) {
    return v > 0.f ? 1.f : (v < 0.f ? -1.f : 0.f);
}

// ---------------- small helper kernels ----------------
__global__ void zero_stats_kernel() {
    int i = threadIdx.x;
    if (i < 142) { d_sum[i] = 0.0; d_sumsq[i] = 0.0; }
}

__global__ void sign_w3_kernel(const float* __restrict__ w) {
    int i = blockIdx.x * blockDim.x + threadIdx.x;
    if (i < 120 * 400) d_w3s[i] = fsign(w[i]);
}

// per-channel sum/sumsq over [B, C, S] layout; grid = (C, NY)
__global__ void stats_kernel(const float* __restrict__ x, int C, int S,
                             int perchan, int off) {
    int c = blockIdx.x;
    int tid = threadIdx.x;
    double s = 0.0, s2 = 0.0;
    int stride = gridDim.y * blockDim.x;
    for (int i = blockIdx.y * blockDim.x + tid; i < perchan; i += stride) {
        int b = i / S;
        int sp = i - b * S;
        float v = x[(b * C + c) * S + sp];
        s += (double)v;
        s2 += (double)v * (double)v;
    }
    __shared__ double sh[256], sh2[256];
    sh[tid] = s; sh2[tid] = s2;
    __syncthreads();
    for (int o = 128; o > 0; o >>= 1) {
        if (tid < o) { sh[tid] += sh[tid + o]; sh2[tid] += sh2[tid + o]; }
        __syncthreads();
    }
    if (tid == 0) {
        atomicAdd(&d_sum[off + c], sh[0]);
        atomicAdd(&d_sumsq[off + c], sh2[0]);
    }
}

__global__ void finalize_kernel(int off, int cnt, double n, double eps,
                                const float* __restrict__ g,
                                const float* __restrict__ beta) {
    int i = threadIdx.x;
    if (i < cnt) {
        double m   = d_sum[off + i] / n;
        double var = d_sumsq[off + i] / n - m * m;
        double inv = 1.0 / sqrt(var + eps);
        float gamma = g ? fmaxf(g[i], 0.01f) : 1.f;
        float a = (float)inv * gamma;
        d_bnA[off + i] = a;
        d_bnC[off + i] = (beta ? beta[i] : 0.f) - (float)m * a;
    }
}

// fused maxpool2x2 + BN(a,c) + relu  (valid since a > 0 => monotone)
__global__ void bnpool_kernel(const float* __restrict__ in, float* __restrict__ out,
                              int C, int IH, int IW, int off, int total) {
    int idx = blockIdx.x * blockDim.x + threadIdx.x;
    if (idx >= total) return;
    int OW = IW >> 1, OH = IH >> 1;
    int ow = idx % OW;
    int r = idx / OW;
    int oh = r % OH; r /= OH;
    int c = r % C;
    int b = r / C;
    const float* p = &in[((b * C + c) * IH + 2 * oh) * IW + 2 * ow];
    float m = fmaxf(fmaxf(p[0], p[1]), fmaxf(p[IW], p[IW + 1]));
    out[idx] = fmaxf(d_bnA[off + c] * m + d_bnC[off + c], 0.f);
}

// ---------------- conv1: 1->6, 5x5 on 32x32 -> [B,6,28,28] ----------------
// one block per image, 192 threads; active t<168 -> (c = t/28, oy = t%28),
// each thread computes one full output row (28) with input row in registers.
__global__ void conv1_kernel(const float* __restrict__ x, const float* __restrict__ w) {
    int b = blockIdx.x, t = threadIdx.x;
    __shared__ float in_s[1024];
    __shared__ float w_s[160];
    for (int i = t; i < 1024; i += 192) in_s[i] = x[b * 1024 + i];
    if (t < 150) w_s[t] = w[t];
    __syncthreads();
    if (t >= 168) return;
    int c = t / 28, oy = t % 28;
    float acc[28];
#pragma unroll
    for (int i = 0; i < 28; i++) acc[i] = 0.f;
#pragma unroll
    for (int ky = 0; ky < 5; ky++) {
        float r[32];
#pragma unroll
        for (int j = 0; j < 32; j++) r[j] = in_s[(oy + ky) * 32 + j];
        const float* wp = &w_s[c * 25 + ky * 5];
        float w0 = wp[0], w1 = wp[1], w2 = wp[2], w3 = wp[3], w4 = wp[4];
#pragma unroll
        for (int ox = 0; ox < 28; ox++)
            acc[ox] += r[ox] * w0 + r[ox + 1] * w1 + r[ox + 2] * w2
                     + r[ox + 3] * w3 + r[ox + 4] * w4;
    }
    float* o = &d_conv1raw[(b * 6 + c) * 784 + oy * 28];
#pragma unroll
    for (int ox = 0; ox < 28; ox++) o[ox] = acc[ox];
}

// ---------------- conv2: binary 6->16, 5x5 on [B,6,14,14] -> [B,16,10,10] ----
// one block per image, 160 threads: t -> (oc = t/10, oy = t%10); output row regs.
__global__ void conv2_kernel(const float* __restrict__ w) {
    int b = blockIdx.x, t = threadIdx.x;
    __shared__ float in_s[1176];   // 6*14*14
    __shared__ float w_s[2400];    // 16*6*25 binarized
    for (int i = t; i < 1176; i += 160) in_s[i] = d_pool1[b * 1176 + i];
    for (int i = t; i < 2400; i += 160) w_s[i] = fsign(w[i]);
    __syncthreads();
    int oc = t / 10, oy = t % 10;
    float acc[10];
#pragma unroll
    for (int i = 0; i < 10; i++) acc[i] = 0.f;
    for (int ic = 0; ic < 6; ic++) {
#pragma unroll
        for (int ky = 0; ky < 5; ky++) {
            float r[14];
#pragma unroll
            for (int j = 0; j < 14; j++) r[j] = in_s[ic * 196 + (oy + ky) * 14 + j];
            const float* wp = &w_s[oc * 150 + ic * 25 + ky * 5];
            float w0 = wp[0], w1 = wp[1], w2 = wp[2], w3 = wp[3], w4 = wp[4];
#pragma unroll
            for (int ox = 0; ox < 10; ox++)
                acc[ox] += r[ox] * w0 + r[ox + 1] * w1 + r[ox + 2] * w2
                         + r[ox + 3] * w3 + r[ox + 4] * w4;
        }
    }
    float* o = &d_conv2raw[(b * 16 + oc) * 100 + oy * 10];
#pragma unroll
    for (int ox = 0; ox < 10; ox++) o[ox] = acc[ox];
}

// ---------------- conv3: binary GEMM [B,400] x [400,120] -> [B,120] ----------
// block = 256 threads (8 warps) handles 32 images; lane = image, warp strides
// over 4-wide oc chunks; weights read as float4 (warp-uniform broadcast).
__global__ void conv3_kernel() {
    extern __shared__ float sm[];  // 32 * 401 floats (padded stride, bank-safe)
    int t = threadIdx.x;
    int blk = blockIdx.x;
    for (int i = t; i < 12800; i += 256) {
        int img = i / 400, k = i - img * 400;
        sm[img * 401 + k] = d_pool2[blk * 12800 + i];
    }
    __syncthreads();
    int warp = t >> 5, lane = t & 31;
    const float* inp = &sm[lane * 401];
    int bimg = blk * 32 + lane;
    for (int chunk = warp; chunk < 30; chunk += 8) {
        int oc0 = chunk * 4;
        float a0 = 0.f, a1 = 0.f, a2 = 0.f, a3 = 0.f;
        const float* w0 = &d_w3s[(oc0 + 0) * 400];
        const float* w1 = &d_w3s[(oc0 + 1) * 400];
        const float* w2 = &d_w3s[(oc0 + 2) * 400];
        const float* w3 = &d_w3s[(oc0 + 3) * 400];
#pragma unroll 4
        for (int k = 0; k < 400; k += 4) {
            float4 q0 = *(const float4*)&w0[k];
            float4 q1 = *(const float4*)&w1[k];
            float4 q2 = *(const float4*)&w2[k];
            float4 q3 = *(const float4*)&w3[k];
            float v0 = inp[k], v1 = inp[k + 1], v2 = inp[k + 2], v3 = inp[k + 3];
            a0 += q0.x * v0 + q0.y * v1 + q0.z * v2 + q0.w * v3;
            a1 += q1.x * v0 + q1.y * v1 + q1.z * v2 + q1.w * v3;
            a2 += q2.x * v0 + q2.y * v1 + q2.z * v2 + q2.w * v3;
            a3 += q3.x * v0 + q3.y * v1 + q3.z * v2 + q3.w * v3;
        }
        float* o = &d_conv3raw[bimg * 120 + oc0];
        o[0] = a0; o[1] = a1; o[2] = a2; o[3] = a3;
    }
}

// ---------------- fc: bn3+relu -> binary fc1+relu -> fc2 ----------------
// 256 threads = 8 warps, one image per warp
__global__ void fc_kernel(const float* __restrict__ fc1w, const float* __restrict__ fc1b,
                          const float* __restrict__ fc2w, const float* __restrict__ fc2b,
                          float* __restrict__ out) {
    __shared__ float h_s[8][120];
    __shared__ float h1_s[8][84];
    int t = threadIdx.x, warp = t >> 5, lane = t & 31;
    int b = blockIdx.x * 8 + warp;
    for (int k = lane; k < 120; k += 32) {
        float v = d_conv3raw[b * 120 + k];
        h_s[warp][k] = fmaxf(d_bnA[22 + k] * v + d_bnC[22 + k], 0.f);
    }
    __syncwarp();
    for (int oc = lane; oc < 84; oc += 32) {
        float acc = fc1b[oc];
        const float* wr = &fc1w[oc * 120];
#pragma unroll 4
        for (int k = 0; k < 120; k++) acc += fsign(wr[k]) * h_s[warp][k];
        h1_s[warp][oc] = fmaxf(acc, 0.f);
    }
    __syncwarp();
    if (lane < 10) {
        float acc = fc2b[lane];
        const float* wr = &fc2w[lane * 84];
#pragma unroll 4
        for (int k = 0; k < 84; k++) acc += wr[k] * h1_s[warp][k];
        out[b * 10 + lane] = acc;
    }
}

// ---------------- launcher ----------------
extern "C" void kernel_launch(void* const* d_in, const int* in_sizes, int n_in,
                              void* d_out, int out_size) {
    const float* x       = (const float*)d_in[0];
    const float* conv1_w = (const float*)d_in[1];
    const float* conv2_w = (const float*)d_in[3];
    const float* bn2_g   = (const float*)d_in[5];
    const float* bn2_b   = (const float*)d_in[6];
    const float* conv3_w = (const float*)d_in[7];
    const float* bn3_g   = (const float*)d_in[9];
    const float* bn3_b   = (const float*)d_in[10];
    const float* fc1_w   = (const float*)d_in[11];
    const float* fc1_b   = (const float*)d_in[12];
    const float* fc2_w   = (const float*)d_in[13];
    const float* fc2_b   = (const float*)d_in[14];
    float* out = (float*)d_out;

    void *p1, *p2, *p3, *pp1 /*unused*/;
    float *conv1raw, *conv2raw, *conv3raw;
    cudaGetSymbolAddress((void**)&conv1raw, d_conv1raw);
    cudaGetSymbolAddress((void**)&conv2raw, d_conv2raw);
    cudaGetSymbolAddress((void**)&conv3raw, d_conv3raw);
    float *pool1, *pool2;
    cudaGetSymbolAddress((void**)&pool1, d_pool1);
    cudaGetSymbolAddress((void**)&pool2, d_pool2);
    (void)p1; (void)p2; (void)p3; (void)pp1;
    (void)in_sizes; (void)n_in; (void)out_size;

    cudaFuncSetAttribute(conv3_kernel,
                         cudaFuncAttributeMaxDynamicSharedMemorySize, 32 * 401 * 4);

    // reset stat accumulators (replay determinism)
    zero_stats_kernel<<<1, 256>>>();
    sign_w3_kernel<<<(48000 + 255) / 256, 256>>>(conv3_w);

    // layer 1
    conv1_kernel<<<BATCH, 192>>>(x, conv1_w);
    stats_kernel<<<dim3(6, 512), 256>>>(conv1raw, 6, 784, BATCH * 784, 0);
    finalize_kernel<<<1, 32>>>(0, 6, (double)BATCH * 784.0, 1e-4, nullptr, nullptr);
    bnpool_kernel<<<(BATCH * 6 * 196) / 256, 256>>>(conv1raw, pool1, 6, 28, 28, 0,
                                                    BATCH * 6 * 196);
    // layer 2
    conv2_kernel<<<BATCH, 160>>>(conv2_w);
    stats_kernel<<<dim3(16, 128), 256>>>(conv2raw, 16, 100, BATCH * 100, 6);
    finalize_kernel<<<1, 32>>>(6, 16, (double)BATCH * 100.0, 1e-4, bn2_g, bn2_b);
    bnpool_kernel<<<(BATCH * 16 * 25) / 256, 256>>>(conv2raw, pool2, 16, 10, 10, 6,
                                                    BATCH * 16 * 25);
    // layer 3
    conv3_kernel<<<BATCH / 32, 256, 32 * 401 * 4>>>();
    stats_kernel<<<dim3(120, 8), 256>>>(conv3raw, 120, 1, BATCH, 22);
    finalize_kernel<<<1, 128>>>(22, 120, (double)BATCH, 1e-5, bn3_g, bn3_b);

    // layer 4 (fc)
    fc_kernel<<<BATCH / 8, 256>>>(fc1_w, fc1_b, fc2_w, fc2_b, out);
}

// round 2
// speedup vs baseline: 1.7250x; 1.7250x over previous
#include <cuda_runtime.h>
#include <math.h>

#define BATCH 8192

// ---------------- scratch (device globals) ----------------
__device__ float  d_pool1u [BATCH * 6 * 196];    // pooled, pre-BN  [B,6,14,14]
__device__ float  d_pool2u [BATCH * 16 * 25];    // pooled, pre-BN  [B,16,5,5]
__device__ float  d_conv3raw[BATCH * 120];       // [B,120]
__device__ float  d_w2s[16 * 6 * 25];            // binarized conv2 weights
__device__ float  d_w3s[120 * 400];              // binarized conv3 weights
__device__ double d_sum  [142 * 32];             // slotted per-channel sums
__device__ double d_sumsq[142 * 32];
__device__ float  d_bnA[142];                    // per-channel scale  (>0)
__device__ float  d_bnC[142];                    // per-channel shift

__device__ __forceinline__ float fsign(float v) {
    return v > 0.f ? 1.f : (v < 0.f ? -1.f : 0.f);
}

// ---------------- prep: zero stats + binarize w2/w3 ----------------
__global__ void prep_kernel(const float* __restrict__ w2, const float* __restrict__ w3) {
    int stride = gridDim.x * blockDim.x;
    int t = blockIdx.x * blockDim.x + threadIdx.x;
    for (int i = t; i < 142 * 32; i += stride) { d_sum[i] = 0.0; d_sumsq[i] = 0.0; }
    for (int i = t; i < 2400; i += stride)  d_w2s[i] = fsign(w2[i]);
    for (int i = t; i < 48000; i += stride) d_w3s[i] = fsign(w3[i]);
}

__global__ void finalize_kernel(int off, int cnt, double n, double eps,
                                const float* __restrict__ g,
                                const float* __restrict__ beta) {
    int i = threadIdx.x;
    if (i < cnt) {
        double s = 0.0, s2 = 0.0;
#pragma unroll
        for (int k = 0; k < 32; k++) {
            s  += d_sum  [(off + i) * 32 + k];
            s2 += d_sumsq[(off + i) * 32 + k];
        }
        double m   = s / n;
        double var = s2 / n - m * m;
        double inv = 1.0 / sqrt(var + eps);
        float gamma = g ? fmaxf(g[i], 0.01f) : 1.f;
        float a = (float)inv * gamma;
        d_bnA[off + i] = a;
        d_bnC[off + i] = (beta ? beta[i] : 0.f) - (float)m * a;
    }
}

// ---------------- conv1: 1->6, 5x5 on 32x32; fused stats + maxpool ---------
// one block per image, 192 threads; t<168 -> (c=t/28, oy=t%28), full out row.
__global__ void conv1_kernel(const float* __restrict__ x, const float* __restrict__ w) {
    __shared__ float in_s[1024];
    __shared__ float w_s[152];
    __shared__ float raw[4704];          // [6][28][28]
    __shared__ float ps[192], ps2[192];
    int b = blockIdx.x, t = threadIdx.x;
    for (int i = t; i < 1024; i += 192) in_s[i] = x[b * 1024 + i];
    if (t < 150) w_s[t] = w[t];
    __syncthreads();
    float s = 0.f, s2 = 0.f;
    if (t < 168) {
        int c = t / 28, oy = t % 28;
        float acc[28];
#pragma unroll
        for (int i = 0; i < 28; i++) acc[i] = 0.f;
#pragma unroll
        for (int ky = 0; ky < 5; ky++) {
            float r[32];
#pragma unroll
            for (int j = 0; j < 32; j++) r[j] = in_s[(oy + ky) * 32 + j];
            const float* wp = &w_s[c * 25 + ky * 5];
            float w0 = wp[0], w1 = wp[1], w2 = wp[2], w3 = wp[3], w4 = wp[4];
#pragma unroll
            for (int ox = 0; ox < 28; ox++)
                acc[ox] += r[ox] * w0 + r[ox + 1] * w1 + r[ox + 2] * w2
                         + r[ox + 3] * w3 + r[ox + 4] * w4;
        }
        float* rr = &raw[(c * 28 + oy) * 28];
#pragma unroll
        for (int ox = 0; ox < 28; ox++) {
            rr[ox] = acc[ox];
            s += acc[ox];
            s2 += acc[ox] * acc[ox];
        }
    }
    ps[t] = s; ps2[t] = s2;
    __syncthreads();
    if (t < 6) {
        double ds = 0.0, ds2 = 0.0;
#pragma unroll
        for (int i = 0; i < 28; i++) { ds += ps[t * 28 + i]; ds2 += ps2[t * 28 + i]; }
        int slot = b & 31;
        atomicAdd(&d_sum[t * 32 + slot], ds);
        atomicAdd(&d_sumsq[t * 32 + slot], ds2);
    }
    // maxpool 2x2 on raw (pre-BN; BN+relu applied by conv2 at load)
    for (int p = t; p < 1176; p += 192) {
        int px = p % 14;
        int r = p / 14;
        int py = r % 14;
        int c = r / 14;
        const float* q = &raw[(c * 28 + 2 * py) * 28 + 2 * px];
        float m = fmaxf(fmaxf(q[0], q[1]), fmaxf(q[28], q[29]));
        d_pool1u[b * 1176 + p] = m;
    }
}

// ---------------- conv2: binary 6->16, 5x5; fused BN1-load + stats + pool ---
// one block per image, 160 threads: t -> (oc=t/10, oy=t%10).
__global__ void conv2_kernel() {
    __shared__ float in_s[1176];   // bn1+relu applied
    __shared__ float w_s[2400];
    __shared__ float raw[1600];    // [16][10][10]
    __shared__ float ps[160], ps2[160];
    int b = blockIdx.x, t = threadIdx.x;
    for (int i = t; i < 1176; i += 160) {
        int c = i / 196;
        float v = d_pool1u[b * 1176 + i];
        in_s[i] = fmaxf(fmaf(d_bnA[c], v, d_bnC[c]), 0.f);
    }
    for (int i = t; i < 2400; i += 160) w_s[i] = d_w2s[i];
    __syncthreads();
    int oc = t / 10, oy = t % 10;
    float acc[10];
#pragma unroll
    for (int i = 0; i < 10; i++) acc[i] = 0.f;
    for (int ic = 0; ic < 6; ic++) {
#pragma unroll
        for (int ky = 0; ky < 5; ky++) {
            float r[14];
#pragma unroll
            for (int j = 0; j < 14; j++) r[j] = in_s[ic * 196 + (oy + ky) * 14 + j];
            const float* wp = &w_s[oc * 150 + ic * 25 + ky * 5];
            float w0 = wp[0], w1 = wp[1], w2 = wp[2], w3 = wp[3], w4 = wp[4];
#pragma unroll
            for (int ox = 0; ox < 10; ox++)
                acc[ox] += r[ox] * w0 + r[ox + 1] * w1 + r[ox + 2] * w2
                         + r[ox + 3] * w3 + r[ox + 4] * w4;
        }
    }
    float s = 0.f, s2 = 0.f;
    float* rr = &raw[(oc * 10 + oy) * 10];
#pragma unroll
    for (int ox = 0; ox < 10; ox++) {
        rr[ox] = acc[ox];
        s += acc[ox];
        s2 += acc[ox] * acc[ox];
    }
    ps[t] = s; ps2[t] = s2;
    __syncthreads();
    if (t < 16) {
        double ds = 0.0, ds2 = 0.0;
#pragma unroll
        for (int i = 0; i < 10; i++) { ds += ps[t * 10 + i]; ds2 += ps2[t * 10 + i]; }
        int slot = b & 31;
        atomicAdd(&d_sum[(6 + t) * 32 + slot], ds);
        atomicAdd(&d_sumsq[(6 + t) * 32 + slot], ds2);
    }
    for (int p = t; p < 400; p += 160) {
        int px = p % 5;
        int r = p / 5;
        int py = r % 5;
        int c2 = r / 5;
        const float* q = &raw[(c2 * 10 + 2 * py) * 10 + 2 * px];
        float m = fmaxf(fmaxf(q[0], q[1]), fmaxf(q[10], q[11]));
        d_pool2u[b * 400 + p] = m;
    }
}

// ---------------- conv3: binary GEMM [B,400]x[400,120]; BN2-load + stats ----
// block = 256 threads handles 32 images; lane = image.
__global__ void conv3_kernel() {
    extern __shared__ float sm[];  // 32 * 401 floats
    int t = threadIdx.x;
    int blk = blockIdx.x;
    for (int i = t; i < 12800; i += 256) {
        int img = i / 400, k = i - img * 400;
        int c = k / 25;
        float v = d_pool2u[blk * 12800 + i];
        sm[img * 401 + k] = fmaxf(fmaf(d_bnA[6 + c], v, d_bnC[6 + c]), 0.f);
    }
    __syncthreads();
    int warp = t >> 5, lane = t & 31;
    const float* inp = &sm[lane * 401];
    int bimg = blk * 32 + lane;
    int slot = blk & 31;
    for (int chunk = warp; chunk < 30; chunk += 8) {
        int oc0 = chunk * 4;
        float a[4] = {0.f, 0.f, 0.f, 0.f};
        const float* w0 = &d_w3s[(oc0 + 0) * 400];
        const float* w1 = &d_w3s[(oc0 + 1) * 400];
        const float* w2 = &d_w3s[(oc0 + 2) * 400];
        const float* w3 = &d_w3s[(oc0 + 3) * 400];
#pragma unroll 4
        for (int k = 0; k < 400; k += 4) {
            float4 q0 = *(const float4*)&w0[k];
            float4 q1 = *(const float4*)&w1[k];
            float4 q2 = *(const float4*)&w2[k];
            float4 q3 = *(const float4*)&w3[k];
            float v0 = inp[k], v1 = inp[k + 1], v2 = inp[k + 2], v3 = inp[k + 3];
            a[0] += q0.x * v0 + q0.y * v1 + q0.z * v2 + q0.w * v3;
            a[1] += q1.x * v0 + q1.y * v1 + q1.z * v2 + q1.w * v3;
            a[2] += q2.x * v0 + q2.y * v1 + q2.z * v2 + q2.w * v3;
            a[3] += q3.x * v0 + q3.y * v1 + q3.z * v2 + q3.w * v3;
        }
        float* o = &d_conv3raw[bimg * 120 + oc0];
#pragma unroll
        for (int j = 0; j < 4; j++) {
            o[j] = a[j];
            // per-oc stats across the 32 images of this warp
            double ds = (double)a[j];
            double ds2 = (double)a[j] * (double)a[j];
#pragma unroll
            for (int off = 16; off > 0; off >>= 1) {
                ds  += __shfl_xor_sync(0xffffffffu, ds, off);
                ds2 += __shfl_xor_sync(0xffffffffu, ds2, off);
            }
            if (lane == 0) {
                atomicAdd(&d_sum[(22 + oc0 + j) * 32 + slot], ds);
                atomicAdd(&d_sumsq[(22 + oc0 + j) * 32 + slot], ds2);
            }
        }
    }
}

// ---------------- fc: bn3+relu -> binary fc1+relu -> fc2 ----------------
__global__ void fc_kernel(const float* __restrict__ fc1w, const float* __restrict__ fc1b,
                          const float* __restrict__ fc2w, const float* __restrict__ fc2b,
                          float* __restrict__ out) {
    __shared__ float h_s[8][120];
    __shared__ float h1_s[8][84];
    int t = threadIdx.x, warp = t >> 5, lane = t & 31;
    int b = blockIdx.x * 8 + warp;
    for (int k = lane; k < 120; k += 32) {
        float v = d_conv3raw[b * 120 + k];
        h_s[warp][k] = fmaxf(fmaf(d_bnA[22 + k], v, d_bnC[22 + k]), 0.f);
    }
    __syncwarp();
    for (int oc = lane; oc < 84; oc += 32) {
        float acc = fc1b[oc];
        const float* wr = &fc1w[oc * 120];
#pragma unroll 4
        for (int k = 0; k < 120; k++) acc += fsign(wr[k]) * h_s[warp][k];
        h1_s[warp][oc] = fmaxf(acc, 0.f);
    }
    __syncwarp();
    if (lane < 10) {
        float acc = fc2b[lane];
        const float* wr = &fc2w[lane * 84];
#pragma unroll 4
        for (int k = 0; k < 84; k++) acc += wr[k] * h1_s[warp][k];
        out[b * 10 + lane] = acc;
    }
}

// ---------------- launcher ----------------
extern "C" void kernel_launch(void* const* d_in, const int* in_sizes, int n_in,
                              void* d_out, int out_size) {
    const float* x       = (const float*)d_in[0];
    const float* conv1_w = (const float*)d_in[1];
    const float* conv2_w = (const float*)d_in[3];
    const float* bn2_g   = (const float*)d_in[5];
    const float* bn2_b   = (const float*)d_in[6];
    const float* conv3_w = (const float*)d_in[7];
    const float* bn3_g   = (const float*)d_in[9];
    const float* bn3_b   = (const float*)d_in[10];
    const float* fc1_w   = (const float*)d_in[11];
    const float* fc1_b   = (const float*)d_in[12];
    const float* fc2_w   = (const float*)d_in[13];
    const float* fc2_b   = (const float*)d_in[14];
    float* out = (float*)d_out;
    (void)in_sizes; (void)n_in; (void)out_size;

    cudaFuncSetAttribute(conv3_kernel,
                         cudaFuncAttributeMaxDynamicSharedMemorySize, 32 * 401 * 4);

    prep_kernel<<<64, 256>>>(conv2_w, conv3_w);

    conv1_kernel<<<BATCH, 192>>>(x, conv1_w);
    finalize_kernel<<<1, 32>>>(0, 6, (double)BATCH * 784.0, 1e-4, nullptr, nullptr);

    conv2_kernel<<<BATCH, 160>>>();
    finalize_kernel<<<1, 32>>>(6, 16, (double)BATCH * 100.0, 1e-4, bn2_g, bn2_b);

    conv3_kernel<<<BATCH / 32, 256, 32 * 401 * 4>>>();
    finalize_kernel<<<1, 128>>>(22, 120, (double)BATCH, 1e-5, bn3_g, bn3_b);

    fc_kernel<<<BATCH / 8, 256>>>(fc1_w, fc1_b, fc2_w, fc2_b, out);
}

// round 3
// speedup vs baseline: 2.2557x; 1.3076x over previous
#include <cuda_runtime.h>
#include <math.h>

#define BATCH 8192
typedef unsigned long long ULL;

// ---------------- scratch (device globals) ----------------
__device__ float  d_pool1u [BATCH * 6 * 196];    // pooled, pre-BN  [B,6,14,14]
__device__ float  d_pool2u [BATCH * 16 * 25];    // pooled, pre-BN  [B,16,5,5]
__device__ float  d_conv3raw[BATCH * 120];       // [B,120]
__device__ float  d_w2s[16 * 6 * 25];            // binarized conv2 weights
__device__ float  d_w3s[120 * 400];              // binarized conv3 weights
__device__ double d_sum  [142 * 32];             // slotted per-channel sums
__device__ double d_sumsq[142 * 32];
__device__ float  d_bnA[142];                    // per-channel scale (>0)
__device__ float  d_bnC[142];                    // per-channel shift

union F2 { ULL u; float2 f; };

__device__ __forceinline__ ULL fma2(ULL a, ULL b, ULL c) {
    ULL d;
    asm("fma.rn.f32x2 %0, %1, %2, %3;" : "=l"(d) : "l"(a), "l"(b), "l"(c));
    return d;
}
__device__ __forceinline__ ULL ld2(const float2* p) { F2 t; t.f = *p; return t.u; }

__device__ __forceinline__ float fsign(float v) {
    return v > 0.f ? 1.f : (v < 0.f ? -1.f : 0.f);
}

// ---------------- prep: zero stats + binarize w2/w3 ----------------
__global__ void prep_kernel(const float* __restrict__ w2, const float* __restrict__ w3) {
    int stride = gridDim.x * blockDim.x;
    int t = blockIdx.x * blockDim.x + threadIdx.x;
    for (int i = t; i < 142 * 32; i += stride) { d_sum[i] = 0.0; d_sumsq[i] = 0.0; }
    for (int i = t; i < 2400; i += stride)  d_w2s[i] = fsign(w2[i]);
    for (int i = t; i < 48000; i += stride) d_w3s[i] = fsign(w3[i]);
}

__global__ void finalize_kernel(int off, int cnt, double n, double eps,
                                const float* __restrict__ g,
                                const float* __restrict__ beta) {
    int i = threadIdx.x;
    if (i < cnt) {
        double s = 0.0, s2 = 0.0;
#pragma unroll
        for (int k = 0; k < 32; k++) {
            s  += d_sum  [(off + i) * 32 + k];
            s2 += d_sumsq[(off + i) * 32 + k];
        }
        double m   = s / n;
        double var = s2 / n - m * m;
        double inv = 1.0 / sqrt(var + eps);
        float gamma = g ? fmaxf(g[i], 0.01f) : 1.f;
        float a = (float)inv * gamma;
        d_bnA[off + i] = a;
        d_bnC[off + i] = (beta ? beta[i] : 0.f) - (float)m * a;
    }
}

// ---------------- conv1: 1->6, 5x5 on 32x32; f32x2 row-pairs -------------
// 2 images/block, 168 threads: t = img*84 + rp*6 + c ; rp=0..13, c=0..5.
// Each thread computes output rows (2rp, 2rp+1) as f32x2, pools + stats in regs.
__global__ void __launch_bounds__(168) conv1_kernel(const float* __restrict__ x,
                                                    const float* __restrict__ w) {
    __shared__ float2 ep[2][16][33];   // vertical pairs (2p, 2p+1)
    __shared__ float2 op[2][15][33];   // vertical pairs (2p+1, 2p+2)
    __shared__ float2 wp_s[150];       // duplicated weights (w,w)
    __shared__ float ps[168], ps2[168];
    int t = threadIdx.x;
    int b0 = blockIdx.x * 2;

    for (int i = t; i < 2048; i += 168) {
        int img = i >> 10, idx = i & 1023, r = idx >> 5, xx = idx & 31;
        float v = x[(b0 + img) * 1024 + idx];
        ((float*)&ep[img][r >> 1][xx])[r & 1] = v;
        if (r >= 1 && r <= 30)
            ((float*)&op[img][(r - 1) >> 1][xx])[(r & 1) ^ 1] = v;
    }
    if (t < 150) { float wv = w[t]; wp_s[t] = make_float2(wv, wv); }
    __syncthreads();

    int img = t / 84, u = t % 84, rp = u / 6, c = u % 6;
    ULL acc[28];
#pragma unroll
    for (int i = 0; i < 28; i++) acc[i] = 0ull;

#pragma unroll
    for (int ky = 0; ky < 5; ky++) {
        const float2* src = (ky & 1) ? &op[img][rp + (ky >> 1)][0]
                                     : &ep[img][rp + (ky >> 1)][0];
        ULL wreg[5];
#pragma unroll
        for (int j = 0; j < 5; j++) { F2 tw; tw.f = wp_s[c * 25 + ky * 5 + j]; wreg[j] = tw.u; }
        {   // ox 0..13 needs x 0..17
            ULL rv[18];
#pragma unroll
            for (int l = 0; l < 18; l++) rv[l] = ld2(&src[l]);
#pragma unroll
            for (int j = 0; j < 5; j++)
#pragma unroll
                for (int ox = 0; ox < 14; ox++)
                    acc[ox] = fma2(rv[ox + j], wreg[j], acc[ox]);
        }
        {   // ox 14..27 needs x 14..31
            ULL rv[18];
#pragma unroll
            for (int l = 0; l < 18; l++) rv[l] = ld2(&src[14 + l]);
#pragma unroll
            for (int j = 0; j < 5; j++)
#pragma unroll
                for (int ox = 0; ox < 14; ox++)
                    acc[14 + ox] = fma2(rv[ox + j], wreg[j], acc[14 + ox]);
        }
    }

    float s = 0.f, s2 = 0.f;
#pragma unroll
    for (int i = 0; i < 28; i++) {
        F2 a; a.u = acc[i];
        s += a.f.x + a.f.y;
        s2 += a.f.x * a.f.x + a.f.y * a.f.y;
    }
    ps[t] = s; ps2[t] = s2;

    int b = b0 + img;
    float2* outp = (float2*)&d_pool1u[(b * 6 + c) * 196 + rp * 14];
#pragma unroll
    for (int p = 0; p < 14; p += 2) {
        F2 a0, a1, a2_, a3;
        a0.u = acc[2 * p]; a1.u = acc[2 * p + 1];
        a2_.u = acc[2 * p + 2]; a3.u = acc[2 * p + 3];
        float m0 = fmaxf(fmaxf(a0.f.x, a0.f.y), fmaxf(a1.f.x, a1.f.y));
        float m1 = fmaxf(fmaxf(a2_.f.x, a2_.f.y), fmaxf(a3.f.x, a3.f.y));
        outp[p >> 1] = make_float2(m0, m1);
    }
    __syncthreads();
    if (t < 12) {
        int im = t / 6, cc = t % 6;
        double ds = 0.0, ds2 = 0.0;
#pragma unroll
        for (int r2 = 0; r2 < 14; r2++) {
            int u2 = im * 84 + r2 * 6 + cc;
            ds += ps[u2]; ds2 += ps2[u2];
        }
        int slot = (b0 + im) & 31;
        atomicAdd(&d_sum[cc * 32 + slot], ds);
        atomicAdd(&d_sumsq[cc * 32 + slot], ds2);
    }
}

// ---------------- conv2: binary 6->16, 5x5; f32x2 row-pairs --------------
// 2 images/block, 160 threads: t = img*80 + rp*16 + oc ; rp=0..4, oc=0..15.
__global__ void __launch_bounds__(160) conv2_kernel() {
    __shared__ float2 ep[2][6][7][15];
    __shared__ float2 op[2][6][6][15];
    __shared__ float2 wd[16][6][25];     // duplicated binarized weights
    __shared__ float ps[160], ps2[160];
    int t = threadIdx.x;
    int b0 = blockIdx.x * 2;

    for (int i = t; i < 2352; i += 160) {
        int img = i / 1176, k = i % 1176;
        int ic = k / 196, rm = k % 196, rr = rm / 14, xx = rm % 14;
        float v = d_pool1u[(b0 + img) * 1176 + k];
        v = fmaxf(fmaf(d_bnA[ic], v, d_bnC[ic]), 0.f);
        ((float*)&ep[img][ic][rr >> 1][xx])[rr & 1] = v;
        if (rr >= 1 && rr <= 12)
            ((float*)&op[img][ic][(rr - 1) >> 1][xx])[(rr & 1) ^ 1] = v;
    }
    for (int i = t; i < 2400; i += 160) {
        float wv = d_w2s[i];
        ((float2*)wd)[i] = make_float2(wv, wv);
    }
    __syncthreads();

    int img = t / 80, u = t % 80, rp = u / 16, oc = u % 16;
    ULL acc[10];
#pragma unroll
    for (int i = 0; i < 10; i++) acc[i] = 0ull;

    for (int ic = 0; ic < 6; ic++) {
#pragma unroll
        for (int ky = 0; ky < 5; ky++) {
            const float2* src = (ky & 1) ? &op[img][ic][rp + (ky >> 1)][0]
                                         : &ep[img][ic][rp + (ky >> 1)][0];
            ULL rv[14];
#pragma unroll
            for (int l = 0; l < 14; l++) rv[l] = ld2(&src[l]);
#pragma unroll
            for (int j = 0; j < 5; j++) {
                F2 tw; tw.f = wd[oc][ic][ky * 5 + j];
                ULL wj = tw.u;
#pragma unroll
                for (int ox = 0; ox < 10; ox++)
                    acc[ox] = fma2(rv[ox + j], wj, acc[ox]);
            }
        }
    }

    float s = 0.f, s2 = 0.f;
#pragma unroll
    for (int i = 0; i < 10; i++) {
        F2 a; a.u = acc[i];
        s += a.f.x + a.f.y;
        s2 += a.f.x * a.f.x + a.f.y * a.f.y;
    }
    ps[t] = s; ps2[t] = s2;

    int b = b0 + img;
#pragma unroll
    for (int p = 0; p < 5; p++) {
        F2 a0, a1; a0.u = acc[2 * p]; a1.u = acc[2 * p + 1];
        float m = fmaxf(fmaxf(a0.f.x, a0.f.y), fmaxf(a1.f.x, a1.f.y));
        d_pool2u[b * 400 + oc * 25 + rp * 5 + p] = m;
    }
    __syncthreads();
    if (t < 32) {
        int im = t / 16, occ = t % 16;
        double ds = 0.0, ds2 = 0.0;
#pragma unroll
        for (int r2 = 0; r2 < 5; r2++) {
            int u2 = im * 80 + r2 * 16 + occ;
            ds += ps[u2]; ds2 += ps2[u2];
        }
        int slot = (b0 + im) & 31;
        atomicAdd(&d_sum[(6 + occ) * 32 + slot], ds);
        atomicAdd(&d_sumsq[(6 + occ) * 32 + slot], ds2);
    }
}

// ---------------- conv3: binary GEMM [B,400]x[400,120]; f32x2 over k -----
__global__ void conv3_kernel() {
    extern __shared__ float sm[];  // 32 * 402
    int t = threadIdx.x;
    int blk = blockIdx.x;
    for (int i = t; i < 12800; i += 256) {
        int img = i / 400, k = i - img * 400;
        int c = k / 25;
        float v = d_pool2u[blk * 12800 + i];
        sm[img * 402 + k] = fmaxf(fmaf(d_bnA[6 + c], v, d_bnC[6 + c]), 0.f);
    }
    __syncthreads();
    int warp = t >> 5, lane = t & 31;
    const float2* inp = (const float2*)&sm[lane * 402];
    int bimg = blk * 32 + lane;
    int slot = blk & 31;
    for (int chunk = warp; chunk < 30; chunk += 8) {
        int oc0 = chunk * 4;
        ULL a2[4] = {0ull, 0ull, 0ull, 0ull};
        const float4* w0 = (const float4*)&d_w3s[(oc0 + 0) * 400];
        const float4* w1 = (const float4*)&d_w3s[(oc0 + 1) * 400];
        const float4* w2 = (const float4*)&d_w3s[(oc0 + 2) * 400];
        const float4* w3 = (const float4*)&d_w3s[(oc0 + 3) * 400];
#pragma unroll 2
        for (int kk = 0; kk < 100; kk++) {
            ULL v0 = ld2(&inp[2 * kk]);
            ULL v1 = ld2(&inp[2 * kk + 1]);
            float4 q;
            F2 p0, p1;
            q = w0[kk]; p0.f = make_float2(q.x, q.y); p1.f = make_float2(q.z, q.w);
            a2[0] = fma2(v0, p0.u, a2[0]); a2[0] = fma2(v1, p1.u, a2[0]);
            q = w1[kk]; p0.f = make_float2(q.x, q.y); p1.f = make_float2(q.z, q.w);
            a2[1] = fma2(v0, p0.u, a2[1]); a2[1] = fma2(v1, p1.u, a2[1]);
            q = w2[kk]; p0.f = make_float2(q.x, q.y); p1.f = make_float2(q.z, q.w);
            a2[2] = fma2(v0, p0.u, a2[2]); a2[2] = fma2(v1, p1.u, a2[2]);
            q = w3[kk]; p0.f = make_float2(q.x, q.y); p1.f = make_float2(q.z, q.w);
            a2[3] = fma2(v0, p0.u, a2[3]); a2[3] = fma2(v1, p1.u, a2[3]);
        }
        float* o = &d_conv3raw[bimg * 120 + oc0];
#pragma unroll
        for (int j = 0; j < 4; j++) {
            F2 a; a.u = a2[j];
            float aj = a.f.x + a.f.y;
            o[j] = aj;
            double ds = (double)aj;
            double ds2 = (double)aj * (double)aj;
#pragma unroll
            for (int off = 16; off > 0; off >>= 1) {
                ds  += __shfl_xor_sync(0xffffffffu, ds, off);
                ds2 += __shfl_xor_sync(0xffffffffu, ds2, off);
            }
            if (lane == 0) {
                atomicAdd(&d_sum[(22 + oc0 + j) * 32 + slot], ds);
                atomicAdd(&d_sumsq[(22 + oc0 + j) * 32 + slot], ds2);
            }
        }
    }
}

// ---------------- fc: bn3+relu -> binary fc1+relu -> fc2 ----------------
__global__ void fc_kernel(const float* __restrict__ fc1w, const float* __restrict__ fc1b,
                          const float* __restrict__ fc2w, const float* __restrict__ fc2b,
                          float* __restrict__ out) {
    __shared__ float h_s[8][120];
    __shared__ float h1_s[8][84];
    int t = threadIdx.x, warp = t >> 5, lane = t & 31;
    int b = blockIdx.x * 8 + warp;
    for (int k = lane; k < 120; k += 32) {
        float v = d_conv3raw[b * 120 + k];
        h_s[warp][k] = fmaxf(fmaf(d_bnA[22 + k], v, d_bnC[22 + k]), 0.f);
    }
    __syncwarp();
    for (int oc = lane; oc < 84; oc += 32) {
        float acc = fc1b[oc];
        const float* wr = &fc1w[oc * 120];
#pragma unroll 4
        for (int k = 0; k < 120; k++) acc += fsign(wr[k]) * h_s[warp][k];
        h1_s[warp][oc] = fmaxf(acc, 0.f);
    }
    __syncwarp();
    if (lane < 10) {
        float acc = fc2b[lane];
        const float* wr = &fc2w[lane * 84];
#pragma unroll 4
        for (int k = 0; k < 84; k++) acc += wr[k] * h1_s[warp][k];
        out[b * 10 + lane] = acc;
    }
}

// ---------------- launcher ----------------
extern "C" void kernel_launch(void* const* d_in, const int* in_sizes, int n_in,
                              void* d_out, int out_size) {
    const float* x       = (const float*)d_in[0];
    const float* conv1_w = (const float*)d_in[1];
    const float* conv2_w = (const float*)d_in[3];
    const float* bn2_g   = (const float*)d_in[5];
    const float* bn2_b   = (const float*)d_in[6];
    const float* conv3_w = (const float*)d_in[7];
    const float* bn3_g   = (const float*)d_in[9];
    const float* bn3_b   = (const float*)d_in[10];
    const float* fc1_w   = (const float*)d_in[11];
    const float* fc1_b   = (const float*)d_in[12];
    const float* fc2_w   = (const float*)d_in[13];
    const float* fc2_b   = (const float*)d_in[14];
    float* out = (float*)d_out;
    (void)in_sizes; (void)n_in; (void)out_size;

    cudaFuncSetAttribute(conv3_kernel,
                         cudaFuncAttributeMaxDynamicSharedMemorySize, 32 * 402 * 4);

    prep_kernel<<<64, 256>>>(conv2_w, conv3_w);

    conv1_kernel<<<BATCH / 2, 168>>>(x, conv1_w);
    finalize_kernel<<<1, 32>>>(0, 6, (double)BATCH * 784.0, 1e-4, nullptr, nullptr);

    conv2_kernel<<<BATCH / 2, 160>>>();
    finalize_kernel<<<1, 32>>>(6, 16, (double)BATCH * 100.0, 1e-4, bn2_g, bn2_b);

    conv3_kernel<<<BATCH / 32, 256, 32 * 402 * 4>>>();
    finalize_kernel<<<1, 128>>>(22, 120, (double)BATCH, 1e-5, bn3_g, bn3_b);

    fc_kernel<<<BATCH / 8, 256>>>(fc1_w, fc1_b, fc2_w, fc2_b, out);
}